// round 7
// baseline (speedup 1.0000x reference)
#include <cuda_runtime.h>

#define TT 2048
#define BB 4096
#define NTH 256
#define NCTA 128

typedef unsigned long long u64;

static __device__ __forceinline__ u64 pk2(float x, float y){
    u64 r; asm("mov.b64 %0,{%1,%2};" : "=l"(r) : "f"(x), "f"(y)); return r;
}
static __device__ __forceinline__ void up2(u64 v, float &x, float &y){
    asm("mov.b64 {%0,%1},%2;" : "=f"(x), "=f"(y) : "l"(v));
}
static __device__ __forceinline__ u64 swp2(u64 v){   // (lo,hi) -> (hi,lo)
    float x, y; up2(v, x, y); return pk2(y, x);
}
static __device__ __forceinline__ u64 fma2(u64 a, u64 b, u64 c){
    u64 d; asm("fma.rn.f32x2 %0,%1,%2,%3;" : "=l"(d) : "l"(a), "l"(b), "l"(c)); return d;
}
static __device__ __forceinline__ u64 add2(u64 a, u64 b){
    u64 d; asm("add.rn.f32x2 %0,%1,%2;" : "=l"(d) : "l"(a), "l"(b)); return d;
}
static __device__ __forceinline__ u64 mul2(u64 a, u64 b){
    u64 d; asm("mul.rn.f32x2 %0,%1,%2;" : "=l"(d) : "l"(a), "l"(b)); return d;
}
static __device__ __forceinline__ u64 relu2(u64 a){
    float x, y; up2(a, x, y);
    return pk2(fmaxf(x, 0.f), fmaxf(y, 0.f));
}
static __device__ __forceinline__ float pick4(float a, float b, float c, float d, int s){
    float x = (s & 1) ? b : a;
    float y = (s & 1) ? d : c;
    return (s & 2) ? y : x;
}

__global__ __launch_bounds__(NTH, 1)
void garch_pinn_kernel(
    const float* __restrict__ returns, const float* __restrict__ log_rv,
    const float* __restrict__ omega_p, const float* __restrict__ beta_p,
    const float* __restrict__ tau1_p, const float* __restrict__ tau2_p,
    const float* __restrict__ gamma_p, const float* __restrict__ xi_p,
    const float* __restrict__ phi_p, const float* __restrict__ d1_p,
    const float* __restrict__ d2_p, const float* __restrict__ mu_p,
    const float* __restrict__ W1, const float* __restrict__ b1,
    const float* __restrict__ W2, const float* __restrict__ b2,
    const float* __restrict__ W3, const float* __restrict__ b3_p,
    float* __restrict__ out)
{
    // per-warp DOUBLE-BUFFERED h1 tile, natural batch pairs; 2 KB/warp
    __shared__ __align__(16) float4 sh1[8][2][64];
    // per-warp output staging: [warp][arr*4+b][33] (pad 33 -> conflict-free)
    __shared__ float obuf[8][16][33];

    const int tid = threadIdx.x;
    const int w = tid >> 5;
    const int l = tid & 31;

    // ---- persistent W2 in registers: lane owns output columns l and l+32 ----
    u64 wreg[64];
    #pragma unroll
    for (int i = 0; i < 64; i++)
        wreg[i] = pk2(W2[i * 64 + l], W2[i * 64 + l + 32]);

    // layer-1 / layer-3 per-lane constants
    const float w1a0 = W1[0 * 64 + l],      w1a1 = W1[1 * 64 + l],      w1a2 = W1[2 * 64 + l];
    const float w1b0 = W1[0 * 64 + l + 32], w1b1 = W1[1 * 64 + l + 32], w1b2 = W1[2 * 64 + l + 32];
    const float b1a = b1[l], b1b = b1[l + 32];
    const u64 w3pair = pk2(W3[l], W3[l + 32]);
    const u64 b2pair = pk2(b2[l], b2[l + 32]);

    const float omega = *omega_p, beta = *beta_p, tau1 = *tau1_p, tau2 = *tau2_p;
    const float gam = *gamma_p, xi = *xi_p, phi = *phi_p;
    const float d1 = *d1_p, d2 = *d2_p, mu = *mu_p, b3 = *b3_p;
    const float beta001 = beta * 0.01f;    // fold: lh' = base + beta*0.01*(tot+b3)

    // this warp's 4 batch chains
    const long bg = (long)blockIdx.x * 32 + w * 4;
    const float* rp = returns + bg * TT;
    const float* lp = log_rv + bg * TT;
    const long BT = (long)BB * TT;

    float lh[4], rcur[4], lcur[4];
    #pragma unroll
    for (int b = 0; b < 4; b++) {
        rcur[b] = rp[b * TT];
        lcur[b] = lp[b * TT];
        lh[b] = lcur[b];     // log(mean(exp(lrv0))) == lrv0
    }

    float* obw = &obuf[w][0][0];

    for (int t = 0; t < TT; t++) {
        float4* sA = &sh1[w][t & 1][0];
        const ulonglong2* hA = reinterpret_cast<const ulonglong2*>(sA);

        // prefetch next step inputs (L1-resident)
        const int tn = (t + 1 < TT) ? t + 1 : t;
        float rnxt[4], lnxt[4];
        #pragma unroll
        for (int b = 0; b < 4; b++) { rnxt[b] = rp[b * TT + tn]; lnxt[b] = lp[b * TT + tn]; }

        // ---- measurement (redundant in every lane; trivial flops) ----
        float z[4], u[4], base[4];
        #pragma unroll
        for (int b = 0; b < 4; b++) {
            float e = __expf(-0.5f * lh[b]);
            z[b] = (rcur[b] - mu) * e;
            float z2m1 = z[b] * z[b] - 1.0f;
            float s = xi + phi * lh[b] + d1 * z[b] + d2 * z2m1;
            u[b] = lcur[b] - s;          // log_x == lcur exactly
            // recurrence base: everything except the NN contribution
            float nb = fmaf(beta, lh[b], omega);
            nb = fmaf(tau1, z[b], nb);
            nb = fmaf(tau2, z2m1, nb);
            nb = fmaf(gam, u[b], nb);
            base[b] = fmaf(beta001, b3, nb);
        }

        // ---- layer 1: this lane's two rows (l and l+32), all 4 batches ----
        float va[4], vb[4];
        #pragma unroll
        for (int b = 0; b < 4; b++) {
            float t0 = fmaf(w1a0, lh[b], b1a);
            t0 = fmaf(w1a1, z[b], t0);
            t0 = fmaf(w1a2, u[b], t0);
            va[b] = fmaxf(t0, 0.0f);
            float t1 = fmaf(w1b0, lh[b], b1b);
            t1 = fmaf(w1b1, z[b], t1);
            t1 = fmaf(w1b2, u[b], t1);
            vb[b] = fmaxf(t1, 0.0f);
        }

        sA[l]      = make_float4(va[0], va[1], va[2], va[3]);   // natural pairs
        sA[l + 32] = make_float4(vb[0], vb[1], vb[2], vb[3]);

        // stage the reduction-independent outputs NOW (fills latency shadows):
        // lanes 4..15: arr = l>>2 in {1,2,3} = (log_x, z, u), batch = l&3
        {
            const int bsel = l & 3;
            float v_lx = pick4(lcur[0], lcur[1], lcur[2], lcur[3], bsel);
            float v_z  = pick4(z[0], z[1], z[2], z[3], bsel);
            float v_u  = pick4(u[0], u[1], u[2], u[3], bsel);
            float v = pick4(v_lx, v_lx, v_z, v_u, l >> 2);  // arr 1,2,3
            if (l >= 4 && l < 16) obw[l * 33 + (t & 31)] = v;
        }
        __syncwarp();

        // ---- layer 2: 64x64. W2 in regs; h natural pairs; split accums ----
        u64 aA0 = b2pair, aB0 = b2pair, aC0 = b2pair, aD0 = b2pair;
        u64 aA1 = 0ull,   aB1 = 0ull,   aC1 = 0ull,   aD1 = 0ull;
        #pragma unroll
        for (int i = 0; i < 32; i++) {
            ulonglong2 P = hA[i];            // broadcast
            u64 s01 = swp2(P.x), s23 = swp2(P.y);
            aA0 = fma2(P.x, wreg[i], aA0);
            aB0 = fma2(s01, wreg[i], aB0);
            aC0 = fma2(P.y, wreg[i], aC0);
            aD0 = fma2(s23, wreg[i], aD0);
            ulonglong2 Q = hA[i + 32];
            u64 q01 = swp2(Q.x), q23 = swp2(Q.y);
            aA1 = fma2(Q.x, wreg[i + 32], aA1);
            aB1 = fma2(q01, wreg[i + 32], aB1);
            aC1 = fma2(Q.y, wreg[i + 32], aC1);
            aD1 = fma2(q23, wreg[i + 32], aD1);
        }
        u64 accA = add2(aA0, aA1), accB = add2(aB0, aB1);
        u64 accC = add2(aC0, aC1), accD = add2(aD0, aD1);

        // ---- layer 3 partial: relu + dot(W3) + component reassembly ----
        u64 ptA = mul2(relu2(accA), w3pair);   // (c[l][b0], c[l32][b1])
        u64 ptB = mul2(relu2(accB), w3pair);   // (c[l][b1], c[l32][b0])
        u64 ptC = mul2(relu2(accC), w3pair);
        u64 ptD = mul2(relu2(accD), w3pair);
        u64 pair01 = add2(ptA, swp2(ptB));     // (b0 part, b1 part)
        u64 pair23 = add2(ptC, swp2(ptD));

        // warp all-reduce (packed 2 batches per shfl; two chains overlap)
        #pragma unroll
        for (int s = 16; s > 0; s >>= 1) {
            pair01 = add2(pair01, __shfl_xor_sync(0xffffffffu, pair01, s));
            pair23 = add2(pair23, __shfl_xor_sync(0xffffffffu, pair23, s));
        }
        float tot[4];
        up2(pair01, tot[0], tot[1]);
        up2(pair23, tot[2], tot[3]);

        // stage enh outputs (lanes 0..3 only pay the latency)
        if (l < 4) {
            const int b = l & 3;
            obw[l * 33 + (t & 31)] = fmaf(0.01f, tot[b] + b3, lh[b]);
        }

        // ---- recurrence: single fma after reduction ----
        #pragma unroll
        for (int b = 0; b < 4; b++) {
            lh[b] = fmaf(beta001, tot[b], base[b]);
            rcur[b] = rnxt[b];
            lcur[b] = lnxt[b];
        }

        // ---- coalesced flush every 32 steps ----
        if ((t & 31) == 31) {
            __syncwarp();
            const int t0 = t - 31;
            #pragma unroll
            for (int q = 0; q < 16; q++) {
                const int arr = q >> 2, bsel = q & 3;
                out[(long)arr * BT + (bg + bsel) * TT + t0 + l] = obw[q * 33 + l];
            }
            __syncwarp();
        }
    }
}

extern "C" void kernel_launch(void* const* d_in, const int* in_sizes, int n_in,
                              void* d_out, int out_size)
{
    garch_pinn_kernel<<<NCTA, NTH>>>(
        (const float*)d_in[0],  (const float*)d_in[1],
        (const float*)d_in[2],  (const float*)d_in[3],
        (const float*)d_in[4],  (const float*)d_in[5],
        (const float*)d_in[6],  (const float*)d_in[7],
        (const float*)d_in[8],  (const float*)d_in[9],
        (const float*)d_in[10], (const float*)d_in[11],
        (const float*)d_in[12], (const float*)d_in[13],
        (const float*)d_in[14], (const float*)d_in[15],
        (const float*)d_in[16], (const float*)d_in[17],
        (float*)d_out);
}